// round 10
// baseline (speedup 1.0000x reference)
#include <cuda_runtime.h>
#include <math.h>

#define HW        4096          // H*W
#define CC        3             // channels
#define FF        64            // freq bins
#define BB        32            // batch
#define NSLAB     (BB*CC*FF)    // 6144 (b,c,f) slabs
#define NUM_KEEP  32
#define NKEPT     (NSLAB/2)     // exactly half kept (NUM_KEEP=FF/2)
#define BN_EPS    1e-5f

// Scratch (no device allocation allowed -> __device__ globals)
__device__ float g_pooled[NSLAB];
__device__ int   g_kept[NKEPT];      // compacted kept slab indices
__device__ int   g_dropped[NKEPT];   // compacted dropped slab indices

// Streaming (evict-first) 16B store.
__device__ __forceinline__ void stcs4(float4* p, float4 v) {
    asm volatile("st.global.cs.v4.f32 [%0], {%1,%2,%3,%4};"
                 :: "l"(p), "f"(v.x), "f"(v.y), "f"(v.z), "f"(v.w)
                 : "memory");
}

// ---------------------------------------------------------------------------
// Phase 1 (fused): mean over H*W per slab + zero-fill of x_pruned_2k.
// One block per 2 slabs: 8 front-batched loads + 8 independent zero stores
// (measured 27.9us, ~7.2 TB/s aggregate).
// ---------------------------------------------------------------------------
__global__ void pool_kernel(const float* __restrict__ x,
                            float* __restrict__ out2) {
    const int blk = blockIdx.x;          // slabs 2*blk, 2*blk+1
    const int t = threadIdx.x;           // 0..255
    const size_t base = (size_t)blk * (2 * HW / 4);
    const float4* __restrict__ p = reinterpret_cast<const float4*>(x) + base;
    float4* __restrict__ o2 = reinterpret_cast<float4*>(out2) + base;

    float4 v[8];
#pragma unroll
    for (int i = 0; i < 8; i++)
        v[i] = p[t + i * 256];

    const float4 z = make_float4(0.f, 0.f, 0.f, 0.f);
#pragma unroll
    for (int i = 0; i < 8; i++)
        stcs4(o2 + t + i * 256, z);

    float s0 = 0.f, s1 = 0.f;
#pragma unroll
    for (int i = 0; i < 4; i++)
        s0 += (v[i].x + v[i].y) + (v[i].z + v[i].w);
#pragma unroll
    for (int i = 4; i < 8; i++)
        s1 += (v[i].x + v[i].y) + (v[i].z + v[i].w);

#pragma unroll
    for (int o = 16; o > 0; o >>= 1) {
        s0 += __shfl_xor_sync(0xffffffffu, s0, o);
        s1 += __shfl_xor_sync(0xffffffffu, s1, o);
    }

    __shared__ float ws0[8], ws1[8];
    if ((t & 31) == 0) { ws0[t >> 5] = s0; ws1[t >> 5] = s1; }
    __syncthreads();
    if (t == 0) {
        float a = 0.f, b = 0.f;
#pragma unroll
        for (int i = 0; i < 8; i++) { a += ws0[i]; b += ws1[i]; }
        g_pooled[2 * blk]     = a * (1.0f / HW);
        g_pooled[2 * blk + 1] = b * (1.0f / HW);
    }
}

// ---------------------------------------------------------------------------
// Phase 2: tiny scoring math + top-32; emits COMPACTED kept/dropped index
// lists (exact 32/32 partition per (b,c) row -> no atomics needed).
// ---------------------------------------------------------------------------
__device__ __forceinline__ float sigmoidf(float v) {
    return 1.0f / (1.0f + expf(-v));
}

__global__ void score_kernel(const float* __restrict__ conv_w,
                             const float* __restrict__ conv_b,
                             const float* __restrict__ fc_w,
                             const float* __restrict__ fc_b,
                             const float* __restrict__ conv1_w,
                             const float* __restrict__ conv1_b,
                             const float* __restrict__ convr_w,
                             const float* __restrict__ convr_b,
                             const float* __restrict__ convl_w,
                             const float* __restrict__ convl_b,
                             const float* __restrict__ bn_gamma,
                             const float* __restrict__ bn_beta,
                             const float* __restrict__ bn_mean,
                             const float* __restrict__ bn_var,
                             const float* __restrict__ a_ptr) {
    const int b = blockIdx.x;
    const int g = threadIdx.x;   // 0..63

    __shared__ float pooled[CC][FF];
    __shared__ float xconv[CC][FF];
    __shared__ float scores[CC][FF];
    __shared__ float fin[CC][FF];
    __shared__ float xrc[CC][2][8];
    __shared__ float xrc2[CC][2][8];
    __shared__ float ar[CC][8];
    __shared__ float al[CC][8];

#pragma unroll
    for (int c = 0; c < CC; c++)
        pooled[c][g] = g_pooled[(b * CC + c) * FF + g];
    __syncthreads();

#pragma unroll
    for (int c = 0; c < CC; c++) {
        float s = conv_b[g];
        for (int f = 0; f < FF; f++)
            s = fmaf(pooled[c][f], conv_w[g * FF + f], s);
        xconv[c][g] = s;
    }
    __syncthreads();

#pragma unroll
    for (int c = 0; c < CC; c++) {
        float s = fc_b[g];
        for (int f = 0; f < FF; f++)
            s = fmaf(xconv[c][f], fc_w[g * FF + f], s);
        scores[c][g] = sigmoidf(s);
    }

    if (g < CC * 8) {
        int c = g / 8, i = g % 8;
        float r = 0.f, co = 0.f;
#pragma unroll
        for (int j = 0; j < 8; j++) {
            r  += pooled[c][i * 8 + j];
            co += pooled[c][j * 8 + i];
        }
        xrc[c][0][i] = r * 0.125f;
        xrc[c][1][i] = co * 0.125f;
    }
    __syncthreads();

    if (g < CC * 8) {
        int d = g / 8, i = g % 8;
        float inv = rsqrtf(bn_var[d] + BN_EPS);
#pragma unroll
        for (int s2 = 0; s2 < 2; s2++) {
            float v = conv1_b[d];
#pragma unroll
            for (int c = 0; c < CC; c++)
                v = fmaf(xrc[c][s2][i], conv1_w[d * CC + c], v);
            v = (v - bn_mean[d]) * inv;
            v = v * bn_gamma[d] + bn_beta[d];
            xrc2[d][s2][i] = sigmoidf(v);
        }
    }
    __syncthreads();

    if (g < CC * 8) {
        int d = g / 8, i = g % 8;
        float vr = convr_b[d], vl = convl_b[d];
#pragma unroll
        for (int c = 0; c < CC; c++) {
            vr = fmaf(xrc2[c][0][i], convr_w[d * CC + c], vr);
            vl = fmaf(xrc2[c][1][i], convl_w[d * CC + c], vl);
        }
        ar[d][i] = sigmoidf(vr);
        al[d][i] = sigmoidf(vl);
    }
    __syncthreads();

    const float a = *a_ptr;
    const int i = g >> 3, j = g & 7;
#pragma unroll
    for (int c = 0; c < CC; c++)
        fin[c][g] = a * ar[c][i] * al[c][j] + (1.0f - a) * scores[c][g];
    __syncthreads();

    // Stable rank (ties -> lower index, matches jax top_k). Ranks 0..63 are
    // a permutation, so rank<32 <-> kept; compaction is a perfect partition.
#pragma unroll
    for (int c = 0; c < CC; c++) {
        float v = fin[c][g];
        int rank = 0;
        for (int f = 0; f < FF; f++) {
            float u = fin[c][f];
            rank += (u > v) || (u == v && f < g);
        }
        const int row  = b * CC + c;          // (b,c) row index
        const int slab = row * FF + g;
        if (rank < NUM_KEEP)
            g_kept[row * NUM_KEEP + rank] = slab;
        else
            g_dropped[row * NUM_KEEP + (rank - NUM_KEEP)] = slab;
    }
}

// ---------------------------------------------------------------------------
// Phase 3: x_pruned via compacted lists. Each block: 2 KEPT + 2 DROPPED
// slabs -> per thread: 8 front-batched loads (kept), 8 INDEPENDENT zero
// stores (dropped; issue during load latency), 8 dependent copy stores.
// Exact pool_kernel instruction shape -> same ~7 TB/s mixed regime.
// ---------------------------------------------------------------------------
__global__ void prune_kernel(const float* __restrict__ x,
                             float* __restrict__ out) {
    const int blk = blockIdx.x;          // 0..NKEPT/2-1
    const int t = threadIdx.x;           // 0..255

    const int ks0 = g_kept[2 * blk];
    const int ks1 = g_kept[2 * blk + 1];
    const int ds0 = g_dropped[2 * blk];
    const int ds1 = g_dropped[2 * blk + 1];

    const float4* __restrict__ p = reinterpret_cast<const float4*>(x);
    float4* __restrict__ o = reinterpret_cast<float4*>(out);

    const size_t kb0 = (size_t)ks0 * (HW / 4) + t;
    const size_t kb1 = (size_t)ks1 * (HW / 4) + t;
    const size_t db0 = (size_t)ds0 * (HW / 4) + t;
    const size_t db1 = (size_t)ds1 * (HW / 4) + t;

    // 1) front-batched loads for the two kept slabs
    float4 v[8];
#pragma unroll
    for (int i = 0; i < 4; i++) v[i]     = p[kb0 + i * 256];
#pragma unroll
    for (int i = 0; i < 4; i++) v[4 + i] = p[kb1 + i * 256];

    // 2) independent zero stores for the two dropped slabs (fill the
    //    load-latency window with write traffic)
    const float4 z = make_float4(0.f, 0.f, 0.f, 0.f);
#pragma unroll
    for (int i = 0; i < 4; i++) stcs4(o + db0 + i * 256, z);
#pragma unroll
    for (int i = 0; i < 4; i++) stcs4(o + db1 + i * 256, z);

    // 3) dependent copy stores for kept slabs
#pragma unroll
    for (int i = 0; i < 4; i++) stcs4(o + kb0 + i * 256, v[i]);
#pragma unroll
    for (int i = 0; i < 4; i++) stcs4(o + kb1 + i * 256, v[4 + i]);
}

// ---------------------------------------------------------------------------
extern "C" void kernel_launch(void* const* d_in, const int* in_sizes, int n_in,
                              void* d_out, int out_size) {
    const float* x_freq  = (const float*)d_in[0];
    const float* conv_w  = (const float*)d_in[1];
    const float* conv_b  = (const float*)d_in[2];
    const float* fc_w    = (const float*)d_in[3];
    const float* fc_b    = (const float*)d_in[4];
    const float* conv1_w = (const float*)d_in[5];
    const float* conv1_b = (const float*)d_in[6];
    const float* convr_w = (const float*)d_in[7];
    const float* convr_b = (const float*)d_in[8];
    const float* convl_w = (const float*)d_in[9];
    const float* convl_b = (const float*)d_in[10];
    const float* bn_gamma = (const float*)d_in[11];
    const float* bn_beta  = (const float*)d_in[12];
    const float* bn_mean  = (const float*)d_in[13];
    const float* bn_var   = (const float*)d_in[14];
    const float* a_scalar = (const float*)d_in[15];

    float* out  = (float*)d_out;                       // x_pruned
    float* out2 = (float*)d_out + (size_t)NSLAB * HW;  // x_pruned_2k (zeros)

    pool_kernel<<<NSLAB / 2, 256>>>(x_freq, out2);
    score_kernel<<<BB, FF>>>(conv_w, conv_b, fc_w, fc_b,
                             conv1_w, conv1_b, convr_w, convr_b,
                             convl_w, convl_b,
                             bn_gamma, bn_beta, bn_mean, bn_var, a_scalar);
    prune_kernel<<<NKEPT / 2, 256>>>(x_freq, out);
}

// round 11
// speedup vs baseline: 1.0240x; 1.0240x over previous
#include <cuda_runtime.h>
#include <math.h>

#define HW        4096          // H*W
#define CC        3             // channels
#define FF        64            // freq bins
#define BB        32            // batch
#define NSLAB     (BB*CC*FF)    // 6144 (b,c,f) slabs
#define NUM_KEEP  32
#define NKEPT     (NSLAB/2)     // exactly half kept (NUM_KEEP = FF/2)
#define BN_EPS    1e-5f

// Scratch (no device allocation allowed -> __device__ globals)
__device__ float g_pooled[NSLAB];
__device__ int   g_dropped[NKEPT];   // compacted dropped slab indices

// Streaming (evict-first) 16B store.
__device__ __forceinline__ void stcs4(float4* p, float4 v) {
    asm volatile("st.global.cs.v4.f32 [%0], {%1,%2,%3,%4};"
                 :: "l"(p), "f"(v.x), "f"(v.y), "f"(v.z), "f"(v.w)
                 : "memory");
}

// ---------------------------------------------------------------------------
// Phase 1 (fused, measured 45.2us = 200MB write cap w/ read fully hidden):
//   - 8 front-batched float4 loads of x (2 slabs per block)
//   - 8 independent zero stores to out2 (issue during load latency)
//   - 8 dependent copy stores x -> out1 (unconditional; dropped slabs get
//     re-zeroed by phase 3)
//   - pool reduction
// ---------------------------------------------------------------------------
__global__ void pool_copy_kernel(const float* __restrict__ x,
                                 float* __restrict__ out1,
                                 float* __restrict__ out2) {
    const int blk = blockIdx.x;          // slabs 2*blk, 2*blk+1
    const int t = threadIdx.x;           // 0..255
    const size_t base = (size_t)blk * (2 * HW / 4);
    const float4* __restrict__ p  = reinterpret_cast<const float4*>(x) + base;
    float4* __restrict__ o1 = reinterpret_cast<float4*>(out1) + base;
    float4* __restrict__ o2 = reinterpret_cast<float4*>(out2) + base;

    float4 v[8];
#pragma unroll
    for (int i = 0; i < 8; i++)
        v[i] = p[t + i * 256];

    // Independent zero stores: no scoreboard wait, fill the write pipe now.
    const float4 z = make_float4(0.f, 0.f, 0.f, 0.f);
#pragma unroll
    for (int i = 0; i < 8; i++)
        stcs4(o2 + t + i * 256, z);

    // Dependent copy stores, consume loads as they land.
#pragma unroll
    for (int i = 0; i < 8; i++)
        stcs4(o1 + t + i * 256, v[i]);

    float s0 = 0.f, s1 = 0.f;
#pragma unroll
    for (int i = 0; i < 4; i++)
        s0 += (v[i].x + v[i].y) + (v[i].z + v[i].w);
#pragma unroll
    for (int i = 4; i < 8; i++)
        s1 += (v[i].x + v[i].y) + (v[i].z + v[i].w);

#pragma unroll
    for (int o = 16; o > 0; o >>= 1) {
        s0 += __shfl_xor_sync(0xffffffffu, s0, o);
        s1 += __shfl_xor_sync(0xffffffffu, s1, o);
    }

    __shared__ float ws0[8], ws1[8];
    if ((t & 31) == 0) { ws0[t >> 5] = s0; ws1[t >> 5] = s1; }
    __syncthreads();
    if (t == 0) {
        float a = 0.f, b = 0.f;
#pragma unroll
        for (int i = 0; i < 8; i++) { a += ws0[i]; b += ws1[i]; }
        g_pooled[2 * blk]     = a * (1.0f / HW);
        g_pooled[2 * blk + 1] = b * (1.0f / HW);
    }
}

// ---------------------------------------------------------------------------
// Phase 2: tiny scoring math + top-32; emits COMPACTED dropped-slab list
// (stable rank 0..63 is a permutation -> perfect partition, no atomics).
// ---------------------------------------------------------------------------
__device__ __forceinline__ float sigmoidf(float v) {
    return 1.0f / (1.0f + expf(-v));
}

__global__ void score_kernel(const float* __restrict__ conv_w,
                             const float* __restrict__ conv_b,
                             const float* __restrict__ fc_w,
                             const float* __restrict__ fc_b,
                             const float* __restrict__ conv1_w,
                             const float* __restrict__ conv1_b,
                             const float* __restrict__ convr_w,
                             const float* __restrict__ convr_b,
                             const float* __restrict__ convl_w,
                             const float* __restrict__ convl_b,
                             const float* __restrict__ bn_gamma,
                             const float* __restrict__ bn_beta,
                             const float* __restrict__ bn_mean,
                             const float* __restrict__ bn_var,
                             const float* __restrict__ a_ptr) {
    const int b = blockIdx.x;
    const int g = threadIdx.x;   // 0..63

    __shared__ float pooled[CC][FF];
    __shared__ float xconv[CC][FF];
    __shared__ float scores[CC][FF];
    __shared__ float fin[CC][FF];
    __shared__ float xrc[CC][2][8];
    __shared__ float xrc2[CC][2][8];
    __shared__ float ar[CC][8];
    __shared__ float al[CC][8];

#pragma unroll
    for (int c = 0; c < CC; c++)
        pooled[c][g] = g_pooled[(b * CC + c) * FF + g];
    __syncthreads();

#pragma unroll
    for (int c = 0; c < CC; c++) {
        float s = conv_b[g];
        for (int f = 0; f < FF; f++)
            s = fmaf(pooled[c][f], conv_w[g * FF + f], s);
        xconv[c][g] = s;
    }
    __syncthreads();

#pragma unroll
    for (int c = 0; c < CC; c++) {
        float s = fc_b[g];
        for (int f = 0; f < FF; f++)
            s = fmaf(xconv[c][f], fc_w[g * FF + f], s);
        scores[c][g] = sigmoidf(s);
    }

    if (g < CC * 8) {
        int c = g / 8, i = g % 8;
        float r = 0.f, co = 0.f;
#pragma unroll
        for (int j = 0; j < 8; j++) {
            r  += pooled[c][i * 8 + j];
            co += pooled[c][j * 8 + i];
        }
        xrc[c][0][i] = r * 0.125f;
        xrc[c][1][i] = co * 0.125f;
    }
    __syncthreads();

    if (g < CC * 8) {
        int d = g / 8, i = g % 8;
        float inv = rsqrtf(bn_var[d] + BN_EPS);
#pragma unroll
        for (int s2 = 0; s2 < 2; s2++) {
            float v = conv1_b[d];
#pragma unroll
            for (int c = 0; c < CC; c++)
                v = fmaf(xrc[c][s2][i], conv1_w[d * CC + c], v);
            v = (v - bn_mean[d]) * inv;
            v = v * bn_gamma[d] + bn_beta[d];
            xrc2[d][s2][i] = sigmoidf(v);
        }
    }
    __syncthreads();

    if (g < CC * 8) {
        int d = g / 8, i = g % 8;
        float vr = convr_b[d], vl = convl_b[d];
#pragma unroll
        for (int c = 0; c < CC; c++) {
            vr = fmaf(xrc2[c][0][i], convr_w[d * CC + c], vr);
            vl = fmaf(xrc2[c][1][i], convl_w[d * CC + c], vl);
        }
        ar[d][i] = sigmoidf(vr);
        al[d][i] = sigmoidf(vl);
    }
    __syncthreads();

    const float a = *a_ptr;
    const int i = g >> 3, j = g & 7;
#pragma unroll
    for (int c = 0; c < CC; c++)
        fin[c][g] = a * ar[c][i] * al[c][j] + (1.0f - a) * scores[c][g];
    __syncthreads();

    // Stable rank (ties -> lower index, matches jax top_k).
#pragma unroll
    for (int c = 0; c < CC; c++) {
        float v = fin[c][g];
        int rank = 0;
        for (int f = 0; f < FF; f++) {
            float u = fin[c][f];
            rank += (u > v) || (u == v && f < g);
        }
        const int row = b * CC + c;
        if (rank >= NUM_KEEP)
            g_dropped[row * NUM_KEEP + (rank - NUM_KEEP)] = row * FF + g;
    }
}

// ---------------------------------------------------------------------------
// Phase 3: re-zero the dropped slabs of out1 via the compacted list.
// Dense pure-store kernel: every block zeroes 2 dropped slabs (32KB), no
// loads, no dead blocks. 50MB @ write cap ~4.5 TB/s -> ~11us.
// ---------------------------------------------------------------------------
__global__ void zero_dropped_kernel(float* __restrict__ out1) {
    const int blk = blockIdx.x;          // 0..NKEPT/2-1
    const int t = threadIdx.x;           // 0..255

    const int ds0 = g_dropped[2 * blk];
    const int ds1 = g_dropped[2 * blk + 1];

    float4* __restrict__ o = reinterpret_cast<float4*>(out1);
    const size_t b0 = (size_t)ds0 * (HW / 4) + t;
    const size_t b1 = (size_t)ds1 * (HW / 4) + t;

    const float4 z = make_float4(0.f, 0.f, 0.f, 0.f);
#pragma unroll
    for (int i = 0; i < 4; i++) stcs4(o + b0 + i * 256, z);
#pragma unroll
    for (int i = 0; i < 4; i++) stcs4(o + b1 + i * 256, z);
}

// ---------------------------------------------------------------------------
extern "C" void kernel_launch(void* const* d_in, const int* in_sizes, int n_in,
                              void* d_out, int out_size) {
    const float* x_freq  = (const float*)d_in[0];
    const float* conv_w  = (const float*)d_in[1];
    const float* conv_b  = (const float*)d_in[2];
    const float* fc_w    = (const float*)d_in[3];
    const float* fc_b    = (const float*)d_in[4];
    const float* conv1_w = (const float*)d_in[5];
    const float* conv1_b = (const float*)d_in[6];
    const float* convr_w = (const float*)d_in[7];
    const float* convr_b = (const float*)d_in[8];
    const float* convl_w = (const float*)d_in[9];
    const float* convl_b = (const float*)d_in[10];
    const float* bn_gamma = (const float*)d_in[11];
    const float* bn_beta  = (const float*)d_in[12];
    const float* bn_mean  = (const float*)d_in[13];
    const float* bn_var   = (const float*)d_in[14];
    const float* a_scalar = (const float*)d_in[15];

    float* out1 = (float*)d_out;                       // x_pruned
    float* out2 = (float*)d_out + (size_t)NSLAB * HW;  // x_pruned_2k (zeros)

    pool_copy_kernel<<<NSLAB / 2, 256>>>(x_freq, out1, out2);
    score_kernel<<<BB, FF>>>(conv_w, conv_b, fc_w, fc_b,
                             conv1_w, conv1_b, convr_w, convr_b,
                             convl_w, convl_b,
                             bn_gamma, bn_beta, bn_mean, bn_var, a_scalar);
    zero_dropped_kernel<<<NKEPT / 2, 256>>>(out1);
}